// round 4
// baseline (speedup 1.0000x reference)
#include <cuda_runtime.h>

#define R  2000
#define D  128
#define H  4
#define NMAX 500000

// ---------------- device scratch (no allocations allowed) ----------------
__device__ __align__(16) float g_qvec[D];      // seed query, flattened [128]
__device__ __align__(16) float g_A[D * H];     // A[d][h] = (Wk^T q_h)[d] / sqrt(D)
__device__ __align__(16) float g_c[4];         // bias term of scores per head
__device__ int   g_hist[R];
__device__ int   g_off[R + 1];
__device__ int   g_cursor[R];
__device__ int   g_perm[NMAX];
__device__ float g_deg[R];
__device__ __align__(16) float g_O[R * D];     // PMA output (pre-rFF)
__device__ __align__(16) float g_hfeat[R * D]; // O2 @ Wg^T
__device__ __align__(16) float g_accG[R * D];  // GCN scatter accumulator
__device__ __align__(16) float g_WoT[D * D];
__device__ __align__(16) float g_WgT[D * D];

// ---------------- init: zero accumulators / counters ----------------
__global__ void k_init() {
    int i = blockIdx.x * blockDim.x + threadIdx.x;
    if (i < R * D) g_accG[i] = 0.f;
    if (i < R) { g_deg[i] = 1.0f; g_hist[i] = 0; g_cursor[i] = 0; }
}

// ---------------- prep: q = Wq S + bq ; A = (Wk^T q)/sqrt(D) ; transposes ----------------
__global__ void k_prep(const float* __restrict__ S,  const float* __restrict__ Wq,
                       const float* __restrict__ bq, const float* __restrict__ Wk,
                       const float* __restrict__ bk, const float* __restrict__ Wo,
                       const float* __restrict__ Wg) {
    __shared__ float s_S[D];
    __shared__ float s_q[D];
    int t = threadIdx.x;  // 128 threads
    s_S[t] = S[t];
    __syncthreads();
    float acc = bq[t];
    for (int d = 0; d < D; d++) acc = fmaf(s_S[d], Wq[t * D + d], acc);
    s_q[t] = acc;
    g_qvec[t] = acc;
    __syncthreads();
    const float scale = 0.08838834764831845f;  // 1/sqrt(128)
    int d = t;
    float a0 = 0.f, a1 = 0.f, a2 = 0.f, a3 = 0.f;
    for (int e = 0; e < 32; e++) {
        a0 = fmaf(s_q[0 * 32 + e], Wk[(0 * 32 + e) * D + d], a0);
        a1 = fmaf(s_q[1 * 32 + e], Wk[(1 * 32 + e) * D + d], a1);
        a2 = fmaf(s_q[2 * 32 + e], Wk[(2 * 32 + e) * D + d], a2);
        a3 = fmaf(s_q[3 * 32 + e], Wk[(3 * 32 + e) * D + d], a3);
    }
    g_A[d * H + 0] = a0 * scale;
    g_A[d * H + 1] = a1 * scale;
    g_A[d * H + 2] = a2 * scale;
    g_A[d * H + 3] = a3 * scale;
    if (t < H) {
        float cc = 0.f;
        for (int e = 0; e < 32; e++) cc = fmaf(s_q[t * 32 + e], bk[t * 32 + e], cc);
        g_c[t] = cc * scale;
    }
    // transpose Wo, Wg for coalesced column access in k_ff
    for (int i = t; i < D * D; i += blockDim.x) {
        int j = i >> 7, dd = i & 127;
        g_WoT[dd * D + j] = Wo[i];
        g_WgT[dd * D + j] = Wg[i];
    }
}

// ---------------- zone histogram + in-degree (fused) ----------------
__global__ void k_hist_deg(const int* __restrict__ zone, const int* __restrict__ adj,
                           int N, int E) {
    int i = blockIdx.x * blockDim.x + threadIdx.x;
    if (i < N) {
        atomicAdd(&g_hist[zone[i]], 1);
    } else if (i < N + E) {
        int e = i - N;
        atomicAdd(&g_deg[adj[E + e]], 1.0f);
    }
}

// ---------------- exclusive scan over hist (warp-scan, 1024 threads) ----------------
__global__ void k_scan() {
    int t = threadIdx.x, lane = t & 31, w = t >> 5;
    int i0 = 2 * t, i1 = 2 * t + 1;
    int v0 = (i0 < R) ? g_hist[i0] : 0;
    int v1 = (i1 < R) ? g_hist[i1] : 0;
    int s = v0 + v1;
    int incl = s;
    #pragma unroll
    for (int o = 1; o < 32; o <<= 1) {
        int n = __shfl_up_sync(0xffffffffu, incl, o);
        if (lane >= o) incl += n;
    }
    __shared__ int wsum[32];
    if (lane == 31) wsum[w] = incl;
    __syncthreads();
    if (w == 0) {
        int wi = wsum[lane];
        #pragma unroll
        for (int o = 1; o < 32; o <<= 1) {
            int n = __shfl_up_sync(0xffffffffu, wi, o);
            if (lane >= o) wi += n;
        }
        wsum[lane] = wi;
    }
    __syncthreads();
    int excl = incl - s + (w ? wsum[w - 1] : 0);
    if (i0 <= R) g_off[i0] = excl;
    if (i1 <= R) g_off[i1] = excl + v0;
}

// ---------------- scatter permutation (counting sort by zone) ----------------
__global__ void k_scatter(const int* __restrict__ zone, int N) {
    int i = blockIdx.x * blockDim.x + threadIdx.x;
    if (i < N) {
        int z = zone[i];
        int p = atomicAdd(&g_cursor[z], 1);
        g_perm[g_off[z] + p] = i;
    }
}

// ---------------- per-region softmax-weighted centroid + Wv matvec ----------------
// lane=row scheme: each warp stages a 32-row x tile into padded smem (cp.async),
// phase1: lane computes its OWN row's 4 head scores (no shuffles, 1 exp/row),
// phase2: lane owns 4 dims and accumulates sum(e*x) over the tile via e-broadcast.
// Single pass over x; normalize at the end (scores are O(0.05), no max needed).
#define TPAD 132   // floats per tile row (528 B, 16B aligned, conflict-free both phases)
__global__ void __launch_bounds__(256) k_region(const float* __restrict__ x,
                                                const float* __restrict__ Wv,
                                                const float* __restrict__ bv) {
    extern __shared__ float dyn[];
    float* s_tiles = dyn;                       // [8][32][TPAD]  = 33792 floats
    float* s_accp  = dyn + 8 * 32 * TPAD;       // [8][4][128]    = 4096
    float* s_e     = s_accp + 8 * 4 * 128;      // [8][32*4]      = 1024
    float* s_Af    = s_e + 8 * 128;             // [128][4]       = 512
    float* s_pool  = s_Af + 512;                // [512]
    float* s_dtot  = s_pool + 512;              // [4]
    float* s_den   = s_dtot + 4;                // [32]

    int tid = threadIdx.x, lane = tid & 31, warp = tid >> 5;
    int r = blockIdx.x;

    if (tid < 128) *(float4*)&s_Af[tid * 4] = *(const float4*)&g_A[tid * 4];
    __syncthreads();

    float4 c4 = *(const float4*)g_c;
    float* tile = s_tiles + warp * (32 * TPAD);
    unsigned tile_u32 = (unsigned)__cvta_generic_to_shared(tile);

    float4 acc0 = make_float4(0.f, 0.f, 0.f, 0.f);
    float4 acc1 = acc0, acc2 = acc0, acc3 = acc0;
    float4 den  = acc0;

    int beg = g_off[r], end = g_off[r + 1];
    for (int t0 = beg + warp * 32; t0 < end; t0 += 256) {
        int vcnt = end - t0; if (vcnt > 32) vcnt = 32;
        int my_idx = (lane < vcnt) ? g_perm[t0 + lane] : 0;
        // --- stage tile: row rr staged cooperatively by all 32 lanes (512B coalesced)
        for (int rr = 0; rr < vcnt; rr++) {
            int irow = __shfl_sync(0xffffffffu, my_idx, rr);
            const float* src = x + (size_t)irow * 128 + lane * 4;
            unsigned dst = tile_u32 + (unsigned)(rr * (TPAD * 4) + lane * 16);
            asm volatile("cp.async.cg.shared.global [%0], [%1], 16;\n"
                         :: "r"(dst), "l"(src) : "memory");
        }
        asm volatile("cp.async.commit_group;\n" ::: "memory");
        asm volatile("cp.async.wait_group 0;\n" ::: "memory");
        __syncwarp();

        // --- phase 1: lane scores its own row (4 heads), split accumulators for ILP
        float sa0 = 0.f, sa1 = 0.f, sa2 = 0.f, sa3 = 0.f;
        float sb0 = 0.f, sb1 = 0.f, sb2 = 0.f, sb3 = 0.f;
        const float* myrow = tile + lane * TPAD;
        #pragma unroll 8
        for (int i = 0; i < 32; i++) {
            float4 xv = *(const float4*)&myrow[i * 4];
            float4 A0 = *(const float4*)&s_Af[(4 * i + 0) * 4];
            float4 A1 = *(const float4*)&s_Af[(4 * i + 1) * 4];
            float4 A2 = *(const float4*)&s_Af[(4 * i + 2) * 4];
            float4 A3 = *(const float4*)&s_Af[(4 * i + 3) * 4];
            sa0 = fmaf(xv.x, A0.x, sa0); sa1 = fmaf(xv.x, A0.y, sa1);
            sa2 = fmaf(xv.x, A0.z, sa2); sa3 = fmaf(xv.x, A0.w, sa3);
            sa0 = fmaf(xv.y, A1.x, sa0); sa1 = fmaf(xv.y, A1.y, sa1);
            sa2 = fmaf(xv.y, A1.z, sa2); sa3 = fmaf(xv.y, A1.w, sa3);
            sb0 = fmaf(xv.z, A2.x, sb0); sb1 = fmaf(xv.z, A2.y, sb1);
            sb2 = fmaf(xv.z, A2.z, sb2); sb3 = fmaf(xv.z, A2.w, sb3);
            sb0 = fmaf(xv.w, A3.x, sb0); sb1 = fmaf(xv.w, A3.y, sb1);
            sb2 = fmaf(xv.w, A3.z, sb2); sb3 = fmaf(xv.w, A3.w, sb3);
        }
        float e0 = __expf(sa0 + sb0 + c4.x);
        float e1 = __expf(sa1 + sb1 + c4.y);
        float e2 = __expf(sa2 + sb2 + c4.z);
        float e3 = __expf(sa3 + sb3 + c4.w);
        if (lane >= vcnt) { e0 = 0.f; e1 = 0.f; e2 = 0.f; e3 = 0.f; }
        *(float4*)&s_e[warp * 128 + lane * 4] = make_float4(e0, e1, e2, e3);
        den.x += e0; den.y += e1; den.z += e2; den.w += e3;
        __syncwarp();

        // --- phase 2: lane owns dims [4l..4l+3]; accumulate sum(e * x) over rows
        const float* ewp = s_e + warp * 128;
        const float* xcol = tile + lane * 4;
        for (int rr = 0; rr < vcnt; rr++) {
            float4 ev = *(const float4*)&ewp[rr * 4];
            float4 xv = *(const float4*)&xcol[rr * TPAD];
            acc0.x = fmaf(ev.x, xv.x, acc0.x); acc0.y = fmaf(ev.x, xv.y, acc0.y);
            acc0.z = fmaf(ev.x, xv.z, acc0.z); acc0.w = fmaf(ev.x, xv.w, acc0.w);
            acc1.x = fmaf(ev.y, xv.x, acc1.x); acc1.y = fmaf(ev.y, xv.y, acc1.y);
            acc1.z = fmaf(ev.y, xv.z, acc1.z); acc1.w = fmaf(ev.y, xv.w, acc1.w);
            acc2.x = fmaf(ev.z, xv.x, acc2.x); acc2.y = fmaf(ev.z, xv.y, acc2.y);
            acc2.z = fmaf(ev.z, xv.z, acc2.z); acc2.w = fmaf(ev.z, xv.w, acc2.w);
            acc3.x = fmaf(ev.w, xv.x, acc3.x); acc3.y = fmaf(ev.w, xv.y, acc3.y);
            acc3.z = fmaf(ev.w, xv.z, acc3.z); acc3.w = fmaf(ev.w, xv.w, acc3.w);
        }
        __syncwarp();  // done reading tile before next stage overwrites
    }

    // --- per-warp den reduction (once per region) ---
    #pragma unroll
    for (int o = 16; o > 0; o >>= 1) {
        den.x += __shfl_xor_sync(0xffffffffu, den.x, o);
        den.y += __shfl_xor_sync(0xffffffffu, den.y, o);
        den.z += __shfl_xor_sync(0xffffffffu, den.z, o);
        den.w += __shfl_xor_sync(0xffffffffu, den.w, o);
    }
    if (lane == 0) {
        s_den[warp * 4 + 0] = den.x; s_den[warp * 4 + 1] = den.y;
        s_den[warp * 4 + 2] = den.z; s_den[warp * 4 + 3] = den.w;
    }
    *(float4*)&s_accp[warp * 512 + 0 * 128 + lane * 4] = acc0;
    *(float4*)&s_accp[warp * 512 + 1 * 128 + lane * 4] = acc1;
    *(float4*)&s_accp[warp * 512 + 2 * 128 + lane * 4] = acc2;
    *(float4*)&s_accp[warp * 512 + 3 * 128 + lane * 4] = acc3;
    __syncthreads();
    if (tid < 4) {
        float v = 0.f;
        #pragma unroll
        for (int w = 0; w < 8; w++) v += s_den[w * 4 + tid];
        s_dtot[tid] = fmaxf(v, 1e-30f);
    }
    __syncthreads();
    for (int i = tid; i < 512; i += 256) {
        int h = i >> 7;
        float v = 0.f;
        #pragma unroll
        for (int w = 0; w < 8; w++) v += s_accp[w * 512 + i];
        s_pool[i] = v / s_dtot[h];
    }
    __syncthreads();
    // pooled[j] = Wv[j,:] . xbar[h(j),:] + bv[j] ; O = q + pooled
    if (tid < 128) {
        int j = tid, h = j >> 5;
        const float4* wr = (const float4*)(Wv + (size_t)j * D);
        const float4* xb = (const float4*)(s_pool + h * D);
        float acc = 0.f;
        #pragma unroll 8
        for (int tt = 0; tt < 32; tt++) {
            float4 w = wr[tt]; float4 b = xb[tt];
            acc = fmaf(w.x, b.x, fmaf(w.y, b.y, fmaf(w.z, b.z, fmaf(w.w, b.w, acc))));
        }
        g_O[r * D + j] = g_qvec[j] + acc + bv[j];
    }
}

// ---------------- fused rFF (O += relu(O@Wo^T + bo)) and h = O2 @ Wg^T ----------------
__global__ void __launch_bounds__(256) k_ff(const float* __restrict__ bo) {
    const int RPB = 16, PAD = 20;
    __shared__ __align__(16) float OsmT[128 * PAD];
    __shared__ __align__(16) float O2T[128 * PAD];
    int r0 = blockIdx.x * RPB;
    int tid = threadIdx.x;
    int j = tid & 127;
    int rr0 = (tid >> 7) * 8;

    for (int i = tid; i < RPB * D; i += 256) {
        int rr = i >> 7, d = i & 127;
        OsmT[d * PAD + rr] = g_O[(r0 + rr) * D + d];
    }
    __syncthreads();

    float acc[8];
    #pragma unroll
    for (int k = 0; k < 8; k++) acc[k] = 0.f;
    for (int d = 0; d < D; d++) {
        float w = g_WoT[d * D + j];
        const float4* o4 = (const float4*)&OsmT[d * PAD + rr0];
        float4 oa = o4[0], ob = o4[1];
        acc[0] = fmaf(w, oa.x, acc[0]); acc[1] = fmaf(w, oa.y, acc[1]);
        acc[2] = fmaf(w, oa.z, acc[2]); acc[3] = fmaf(w, oa.w, acc[3]);
        acc[4] = fmaf(w, ob.x, acc[4]); acc[5] = fmaf(w, ob.y, acc[5]);
        acc[6] = fmaf(w, ob.z, acc[6]); acc[7] = fmaf(w, ob.w, acc[7]);
    }
    float boj = bo[j];
    #pragma unroll
    for (int k = 0; k < 8; k++) {
        float t = acc[k] + boj;
        t = t > 0.f ? t : 0.f;
        O2T[j * PAD + rr0 + k] = OsmT[j * PAD + rr0 + k] + t;
    }
    __syncthreads();
    #pragma unroll
    for (int k = 0; k < 8; k++) acc[k] = 0.f;
    for (int d = 0; d < D; d++) {
        float w = g_WgT[d * D + j];
        const float4* o4 = (const float4*)&O2T[d * PAD + rr0];
        float4 oa = o4[0], ob = o4[1];
        acc[0] = fmaf(w, oa.x, acc[0]); acc[1] = fmaf(w, oa.y, acc[1]);
        acc[2] = fmaf(w, oa.z, acc[2]); acc[3] = fmaf(w, oa.w, acc[3]);
        acc[4] = fmaf(w, ob.x, acc[4]); acc[5] = fmaf(w, ob.y, acc[5]);
        acc[6] = fmaf(w, ob.z, acc[6]); acc[7] = fmaf(w, ob.w, acc[7]);
    }
    #pragma unroll
    for (int k = 0; k < 8; k++) g_hfeat[(r0 + rr0 + k) * D + j] = acc[k];
}

// ---------------- GCN edge scatter (incl. self loops) ----------------
__global__ void k_edge(const int* __restrict__ adj, int E) {
    int idx = blockIdx.x * blockDim.x + threadIdx.x;
    int total = (E + R) * 32;
    if (idx >= total) return;
    int e = idx >> 5, g = idx & 31, d0 = g * 4;
    int s, dt;
    if (e < E) { s = adj[e]; dt = adj[E + e]; }
    else       { s = dt = e - E; }
    float nrm = rsqrtf(g_deg[s]) * rsqrtf(g_deg[dt]);
    float4 hv = *(const float4*)&g_hfeat[s * D + d0];
    float* o = &g_accG[dt * D + d0];
    atomicAdd(o + 0, nrm * hv.x);
    atomicAdd(o + 1, nrm * hv.y);
    atomicAdd(o + 2, nrm * hv.z);
    atomicAdd(o + 3, nrm * hv.w);
}

// ---------------- bias + PReLU epilogue ----------------
__global__ void k_prelu(const float* __restrict__ bg, const float* __restrict__ pw,
                        float* __restrict__ out) {
    int i = blockIdx.x * blockDim.x + threadIdx.x;
    if (i < R * D) {
        int d = i & 127;
        float v = g_accG[i] + bg[d];
        out[i] = v > 0.f ? v : pw[d] * v;
    }
}

// ---------------- launcher ----------------
extern "C" void kernel_launch(void* const* d_in, const int* in_sizes, int n_in,
                              void* d_out, int out_size) {
    const float* x  = (const float*)d_in[0];
    const int* zone = (const int*)d_in[1];
    const int* adj  = (const int*)d_in[2];
    const float* S  = (const float*)d_in[3];
    const float* Wq = (const float*)d_in[4];
    const float* bq = (const float*)d_in[5];
    const float* Wk = (const float*)d_in[6];
    const float* bk = (const float*)d_in[7];
    const float* Wv = (const float*)d_in[8];
    const float* bv = (const float*)d_in[9];
    const float* Wo = (const float*)d_in[10];
    const float* bo = (const float*)d_in[11];
    const float* Wg = (const float*)d_in[12];
    const float* bg = (const float*)d_in[13];
    const float* pw = (const float*)d_in[14];
    float* out = (float*)d_out;
    int N = in_sizes[0] / D;
    int E = in_sizes[2] / 2;

    const int SMEM_REGION = (8 * 32 * TPAD + 8 * 4 * 128 + 8 * 128 + 512 + 512 + 4 + 32) * 4;
    cudaFuncSetAttribute(k_region, cudaFuncAttributeMaxDynamicSharedMemorySize, SMEM_REGION);

    k_init<<<(R * D + 255) / 256, 256>>>();
    k_prep<<<1, 128>>>(S, Wq, bq, Wk, bk, Wo, Wg);
    k_hist_deg<<<(N + E + 255) / 256, 256>>>(zone, adj, N, E);
    k_scan<<<1, 1024>>>();
    k_scatter<<<(N + 255) / 256, 256>>>(zone, N);
    k_region<<<R, 256, SMEM_REGION>>>(x, Wv, bv);
    k_ff<<<R / 16, 256>>>(bo);
    k_edge<<<((E + R) * 32 + 255) / 256, 256>>>(adj, E);
    k_prelu<<<(R * D + 255) / 256, 256>>>(bg, pw, out);
}